// round 8
// baseline (speedup 1.0000x reference)
#include <cuda_runtime.h>
#include <cuda_fp16.h>
#include <cstdint>

// ============ helpers ============

__device__ __forceinline__ uint32_t smem_u32(const void* p) {
    uint32_t a;
    asm("{ .reg .u64 t; cvta.to.shared.u64 t, %1; cvt.u32.u64 %0, t; }" : "=r"(a) : "l"(p));
    return a;
}

__device__ __forceinline__ void cp_async16(uint32_t saddr, const void* gaddr) {
    asm volatile("cp.async.cg.shared.global [%0], [%1], 16;" :: "r"(saddr), "l"(gaddr));
}
#define CP_COMMIT() asm volatile("cp.async.commit_group;" ::: "memory")
#define CP_WAIT(N)  asm volatile("cp.async.wait_group %0;" :: "n"(N) : "memory")

__device__ __forceinline__ void ldsm_x4(uint32_t addr, uint32_t& r0, uint32_t& r1,
                                        uint32_t& r2, uint32_t& r3) {
    asm volatile("ldmatrix.sync.aligned.m8n8.x4.shared.b16 {%0,%1,%2,%3}, [%4];"
                 : "=r"(r0), "=r"(r1), "=r"(r2), "=r"(r3) : "r"(addr));
}

__device__ __forceinline__ void lds128(uint32_t addr, uint32_t& x, uint32_t& y,
                                       uint32_t& z, uint32_t& w) {
    asm volatile("ld.shared.v4.b32 {%0,%1,%2,%3}, [%4];"
                 : "=r"(x), "=r"(y), "=r"(z), "=r"(w) : "r"(addr));
}
__device__ __forceinline__ void sts128(uint32_t a, uint32_t x, uint32_t y, uint32_t z, uint32_t w) {
    asm volatile("st.shared.v4.b32 [%0], {%1,%2,%3,%4};"
                 :: "r"(a), "r"(x), "r"(y), "r"(z), "r"(w) : "memory");
}

__device__ __forceinline__ void mma16816(float* c, const uint32_t* a, uint32_t b0, uint32_t b1) {
    asm volatile(
        "mma.sync.aligned.m16n8k16.row.col.f32.f16.f16.f32 "
        "{%0,%1,%2,%3}, {%4,%5,%6,%7}, {%8,%9}, {%0,%1,%2,%3};"
        : "+f"(c[0]), "+f"(c[1]), "+f"(c[2]), "+f"(c[3])
        : "r"(a[0]), "r"(a[1]), "r"(a[2]), "r"(a[3]), "r"(b0), "r"(b1));
}

__device__ __forceinline__ void split2(float v0, float v1, uint32_t& hi, uint32_t& lo) {
    __half h0 = __float2half_rn(v0), h1 = __float2half_rn(v1);
    __half2 hh = __halves2half2(h0, h1);
    hi = *(uint32_t*)&hh;
    __half2 ll = __floats2half2_rn(v0 - __half2float(h0), v1 - __half2float(h1));
    lo = *(uint32_t*)&ll;
}

// ============ device scratch ============

static constexpr size_t NEL = 16ull * 1024 * 1024;  // 16 x 1024 x 1024

__device__ __half g_w[NEL];     // softmax weights, fp16
__device__ __half g_et[NEL];    // E^T per batch, fp16: [b][d][k]
__device__ float  g_scores[NEL];

// gemm2 fp16 MMA tile: 128 rows x 32 halves, stride 80 B (conflict-free LDSM)
static constexpr int ROWB = 80;
static constexpr int TILEB = 128 * ROWB;  // 10240 B

// ---- GEMM1 smem layout (k-chunk 16, double staging + double tiles) ----
static constexpr int G1_SROW = 80;                   // fp32 staging row: 64B data + 16 pad
static constexpr int G1_SOP  = 128 * G1_SROW;        // 10240 per operand
static constexpr int G1_SBUF = 2 * G1_SOP;           // 20480 per stage (A then B)
static constexpr int G1_TROW = 48;                   // fp16 tile row: 32B data + 16 pad (16B-aligned!)
static constexpr int G1_TSZ  = 128 * G1_TROW;        // 6144 per tile
static constexpr int G1_TBASE = 2 * G1_SBUF;         // 40960
static constexpr int G1_SMEM  = G1_TBASE + 2 * 4 * G1_TSZ;  // 90112

// ============ GEMM1: scores = Q @ E^T (3-term fp16 split), fused convert + fused E^T ============
// CTA 128x128, 8 warps (2 M x 4 N), k-chunk 16, 64 chunks, single sync/chunk, 2 CTAs/SM.

__device__ __forceinline__ void g1_cp(uint32_t sb, int tid, int kc, int stage,
                                      const float* gQ, const float* gE) {
    #pragma unroll
    for (int i = 0; i < 2; i++) {
        int id = i * 256 + tid;           // 0..511
        int row = id >> 2, seg = id & 3;
        uint32_t off = (uint32_t)stage * G1_SBUF + row * G1_SROW + seg * 16;
        size_t go = (size_t)row * 1024 + kc * 16 + seg * 4;
        cp_async16(sb + off, gQ + go);
        cp_async16(sb + G1_SOP + off, gE + go);
    }
    CP_COMMIT();
}

__device__ __forceinline__ void g1_convert(uint32_t sb, int tid, int stage) {
    int row = tid & 127, seg = tid >> 7;             // seg 0/1 = k-halves 0..7 / 8..15
    uint32_t csrc = row * G1_SROW + seg * 32;
    uint32_t cdst = row * G1_TROW + seg * 16;
    #pragma unroll
    for (int op = 0; op < 2; op++) {
        uint32_t src = sb + stage * G1_SBUF + op * G1_SOP + csrc;
        uint32_t r[8];
        lds128(src,      r[0], r[1], r[2], r[3]);
        lds128(src + 16, r[4], r[5], r[6], r[7]);
        uint32_t hi[4], lo[4];
        #pragma unroll
        for (int j = 0; j < 4; j++)
            split2(__uint_as_float(r[j * 2]), __uint_as_float(r[j * 2 + 1]), hi[j], lo[j]);
        uint32_t dbase = sb + G1_TBASE + stage * (4 * G1_TSZ) + (op * 2) * G1_TSZ + cdst;
        sts128(dbase,          hi[0], hi[1], hi[2], hi[3]);
        sts128(dbase + G1_TSZ, lo[0], lo[1], lo[2], lo[3]);
    }
}

__global__ void __launch_bounds__(256, 2)
gemm1_kernel(const float* __restrict__ Q, const float* __restrict__ E) {
    extern __shared__ char smem[];
    uint32_t sb = smem_u32(smem);
    int tid = threadIdx.x, wid = tid >> 5, lane = tid & 31;
    int wm = wid >> 2, wn = wid & 3;
    int b = blockIdx.z;
    int m0 = blockIdx.y << 7, n0 = blockIdx.x << 7;
    size_t boff = (size_t)b << 20;

    // ---- fused E^T convert-transpose: this CTA handles block d0=m0, k0=n0 ----
    {
        __half* ts = (__half*)smem;                 // 64 x 65 halves scratch
        int f4id = tid & 15, rr = tid >> 4;
        #pragma unroll
        for (int sub = 0; sub < 4; sub++) {
            int d0 = m0 + (sub >> 1) * 64, k0 = n0 + (sub & 1) * 64;
            #pragma unroll
            for (int pass = 0; pass < 4; pass++) {
                int k = pass * 16 + rr;
                float4 v = *(const float4*)(E + boff + (size_t)(k0 + k) * 1024 + d0 + f4id * 4);
                __half* rp = ts + k * 65 + f4id * 4;
                rp[0] = __float2half_rn(v.x);
                rp[1] = __float2half_rn(v.y);
                rp[2] = __float2half_rn(v.z);
                rp[3] = __float2half_rn(v.w);
            }
            __syncthreads();
            #pragma unroll
            for (int pass = 0; pass < 8; pass++) {
                int dd = pass * 8 + (tid >> 5);
                int kk = lane * 2;
                __half2 o = __halves2half2(ts[kk * 65 + dd], ts[(kk + 1) * 65 + dd]);
                *(__half2*)(g_et + boff + (size_t)(d0 + dd) * 1024 + k0 + kk) = o;
            }
            __syncthreads();
        }
    }

    const float* gQ = Q + boff + (size_t)m0 * 1024;
    const float* gE = E + boff + (size_t)n0 * 1024;

    float c[4][4][4];
    #pragma unroll
    for (int i = 0; i < 4; i++)
        #pragma unroll
        for (int j = 0; j < 4; j++)
            #pragma unroll
            for (int k = 0; k < 4; k++) c[i][j][k] = 0.f;

    // pipeline prologue: chunk0 -> S[0], convert, chunk1 -> S[1] in flight
    g1_cp(sb, tid, 0, 0, gQ, gE);
    CP_WAIT(0);
    __syncthreads();
    g1_convert(sb, tid, 0);
    g1_cp(sb, tid, 1, 1, gQ, gE);

    int lr = lane & 15;
    uint32_t koff = (lane >> 4) * 16;  // k-half byte offset within 32B tile row

    for (int kc = 0; kc < 64; kc++) {
        int s = kc & 1;
        CP_WAIT(0);        // own groups drained -> chunk kc+1 landed (this thread)
        __syncthreads();   // all threads' cps landed; prev interval's MMA/convert done

        if (kc + 2 < 64) g1_cp(sb, tid, kc + 2, s, gQ, gE);   // S[s] free (read last interval)
        if (kc + 1 < 64) g1_convert(sb, tid, s ^ 1);          // S[s^1] -> T[s^1]

        // ---- MMA on T[s] (overlaps other warps' convert via issue interleave) ----
        uint32_t tb = sb + G1_TBASE + s * (4 * G1_TSZ);
        uint32_t bh[2][4], bl[2][4];
        #pragma unroll
        for (int p = 0; p < 2; p++) {
            uint32_t a = tb + 2 * G1_TSZ + (wn * 32 + p * 16 + lr) * G1_TROW + koff;
            ldsm_x4(a, bh[p][0], bh[p][1], bh[p][2], bh[p][3]);
            ldsm_x4(a + G1_TSZ, bl[p][0], bl[p][1], bl[p][2], bl[p][3]);
        }
        #pragma unroll
        for (int mt = 0; mt < 4; mt++) {
            uint32_t ah[4], al[4];
            uint32_t a = tb + (wm * 64 + mt * 16 + lr) * G1_TROW + koff;
            ldsm_x4(a, ah[0], ah[1], ah[2], ah[3]);
            ldsm_x4(a + G1_TSZ, al[0], al[1], al[2], al[3]);
            #pragma unroll
            for (int p = 0; p < 2; p++)
                #pragma unroll
                for (int q = 0; q < 2; q++) {
                    int nt = p * 2 + q;
                    mma16816(c[mt][nt], ah, bh[p][q], bh[p][q + 2]);
                    mma16816(c[mt][nt], ah, bl[p][q], bl[p][q + 2]);
                    mma16816(c[mt][nt], al, bh[p][q], bh[p][q + 2]);
                }
        }
    }

    int r0 = m0 + wm * 64 + (lane >> 2);
    int col = n0 + wn * 32 + (lane & 3) * 2;
    #pragma unroll
    for (int mt = 0; mt < 4; mt++)
        #pragma unroll
        for (int nt = 0; nt < 4; nt++) {
            size_t base = boff + (size_t)(r0 + mt * 16) * 1024 + col + nt * 8;
            *(float2*)(g_scores + base) = make_float2(c[mt][nt][0], c[mt][nt][1]);
            *(float2*)(g_scores + base + 8 * 1024) = make_float2(c[mt][nt][2], c[mt][nt][3]);
        }
}

// ============ softmax: fp32 rows of g_scores -> fp16 g_w ============

__global__ void __launch_bounds__(256)
softmax_kernel() {
    __shared__ float red[40];
    size_t row = blockIdx.x;
    const float4* p = (const float4*)(g_scores + (row << 10));
    int t = threadIdx.x, wid = t >> 5, lane = t & 31;

    float4 v = p[t];
    float m = fmaxf(fmaxf(v.x, v.y), fmaxf(v.z, v.w));
    #pragma unroll
    for (int o = 16; o; o >>= 1) m = fmaxf(m, __shfl_xor_sync(0xffffffffu, m, o));
    if (lane == 0) red[wid] = m;
    __syncthreads();
    if (t == 0) {
        float mm = red[0];
        #pragma unroll
        for (int i = 1; i < 8; i++) mm = fmaxf(mm, red[i]);
        red[8] = mm;
    }
    __syncthreads();
    float mx = red[8];

    float4 e = make_float4(__expf(v.x - mx), __expf(v.y - mx),
                           __expf(v.z - mx), __expf(v.w - mx));
    float s = e.x + e.y + e.z + e.w;
    #pragma unroll
    for (int o = 16; o; o >>= 1) s += __shfl_xor_sync(0xffffffffu, s, o);
    if (lane == 0) red[16 + wid] = s;
    __syncthreads();
    if (t == 0) {
        float ss = red[16];
        #pragma unroll
        for (int i = 1; i < 8; i++) ss += red[16 + i];
        red[24] = 1.0f / ss;
    }
    __syncthreads();
    float inv = red[24];

    __half2* w = (__half2*)(g_w + (row << 10));
    w[t * 2]     = __floats2half2_rn(e.x * inv, e.y * inv);
    w[t * 2 + 1] = __floats2half2_rn(e.z * inv, e.w * inv);
}

// ============ GEMM2: out = W @ V (pure fp16, 3-stage pipeline, g_et from gemm1) ============

__device__ __forceinline__ void g2_load(uint32_t base, int tid, int kc,
                                        const __half* gA, const __half* gB) {
    #pragma unroll
    for (int i = 0; i < 2; i++) {
        int cid = i * 256 + tid;
        int row = cid >> 2, seg = cid & 3;
        uint32_t off = row * ROWB + seg * 16;
        size_t go = (size_t)row * 1024 + kc * 32 + seg * 8;
        cp_async16(base + off, gA + go);
        cp_async16(base + TILEB + off, gB + go);
    }
    CP_COMMIT();
}

__global__ void __launch_bounds__(256, 2)
gemm2_kernel(float* __restrict__ O) {
    extern __shared__ char smem[];
    uint32_t sb = smem_u32(smem);
    int tid = threadIdx.x, wid = tid >> 5, lane = tid & 31;
    int wm = wid >> 2, wn = wid & 3;
    int b = blockIdx.z;
    int m0 = blockIdx.y << 7, n0 = blockIdx.x << 7;
    size_t boff = (size_t)b << 20;

    const __half* gA = g_w + boff + (size_t)m0 * 1024;
    const __half* gB = g_et + boff + (size_t)n0 * 1024;

    float c[4][4][4];
    #pragma unroll
    for (int i = 0; i < 4; i++)
        #pragma unroll
        for (int j = 0; j < 4; j++)
            #pragma unroll
            for (int k = 0; k < 4; k++) c[i][j][k] = 0.f;

    g2_load(sb + 0 * 2 * TILEB, tid, 0, gA, gB);
    g2_load(sb + 1 * 2 * TILEB, tid, 1, gA, gB);

    int lr = lane & 15;
    uint32_t lkoff = (lane >> 4) * 16;

    int slot = 0;
    for (int kc = 0; kc < 32; kc++) {
        if (kc < 31) { CP_WAIT(1); } else { CP_WAIT(0); }
        __syncthreads();

        uint32_t abase = sb + slot * 2 * TILEB;
        #pragma unroll
        for (int ks = 0; ks < 2; ks++) {
            uint32_t koff = ks * 32 + lkoff;
            uint32_t ah[4][4], bh[2][4];
            #pragma unroll
            for (int mt = 0; mt < 4; mt++) {
                uint32_t a = abase + (wm * 64 + mt * 16 + lr) * ROWB + koff;
                ldsm_x4(a, ah[mt][0], ah[mt][1], ah[mt][2], ah[mt][3]);
            }
            #pragma unroll
            for (int p = 0; p < 2; p++) {
                uint32_t a = abase + TILEB + (wn * 32 + p * 16 + lr) * ROWB + koff;
                ldsm_x4(a, bh[p][0], bh[p][1], bh[p][2], bh[p][3]);
            }
            #pragma unroll
            for (int mt = 0; mt < 4; mt++)
                #pragma unroll
                for (int p = 0; p < 2; p++)
                    #pragma unroll
                    for (int q = 0; q < 2; q++)
                        mma16816(c[mt][p * 2 + q], ah[mt], bh[p][q], bh[p][q + 2]);
        }

        if (kc + 2 < 32) {
            int ns = kc + 2 - ((kc + 2) / 3) * 3;  // (kc+2) % 3
            g2_load(sb + ns * 2 * TILEB, tid, kc + 2, gA, gB);
        }
        slot = (slot == 2) ? 0 : slot + 1;
    }

    int r0 = m0 + wm * 64 + (lane >> 2);
    int col = n0 + wn * 32 + (lane & 3) * 2;
    #pragma unroll
    for (int mt = 0; mt < 4; mt++)
        #pragma unroll
        for (int nt = 0; nt < 4; nt++) {
            size_t base = boff + (size_t)(r0 + mt * 16) * 1024 + col + nt * 8;
            *(float2*)(O + base) = make_float2(c[mt][nt][0], c[mt][nt][1]);
            *(float2*)(O + base + 8 * 1024) = make_float2(c[mt][nt][2], c[mt][nt][3]);
        }
}

// ============ launcher ============

extern "C" void kernel_launch(void* const* d_in, const int* in_sizes, int n_in,
                              void* d_out, int out_size) {
    const float* dec = (const float*)d_in[0];   // decoder_hidden  [16,1024,1024]
    const float* enc = (const float*)d_in[1];   // encoder_outputs [16,1024,1024]
    float* out = (float*)d_out;

    cudaFuncSetAttribute(gemm1_kernel, cudaFuncAttributeMaxDynamicSharedMemorySize, G1_SMEM);
    cudaFuncSetAttribute(gemm2_kernel, cudaFuncAttributeMaxDynamicSharedMemorySize, 6 * TILEB);

    gemm1_kernel<<<dim3(8, 8, 16), 256, G1_SMEM>>>(dec, enc);
    softmax_kernel<<<16384, 256>>>();
    gemm2_kernel<<<dim3(8, 8, 16), 256, 6 * TILEB>>>(out);
}

// round 9
// speedup vs baseline: 1.0489x; 1.0489x over previous
#include <cuda_runtime.h>
#include <cuda_fp16.h>
#include <cstdint>

// ============ helpers ============

__device__ __forceinline__ uint32_t smem_u32(const void* p) {
    uint32_t a;
    asm("{ .reg .u64 t; cvta.to.shared.u64 t, %1; cvt.u32.u64 %0, t; }" : "=r"(a) : "l"(p));
    return a;
}

__device__ __forceinline__ void cp_async16(uint32_t saddr, const void* gaddr) {
    asm volatile("cp.async.cg.shared.global [%0], [%1], 16;" :: "r"(saddr), "l"(gaddr));
}
#define CP_COMMIT() asm volatile("cp.async.commit_group;" ::: "memory")
#define CP_WAIT(N)  asm volatile("cp.async.wait_group %0;" :: "n"(N) : "memory")

__device__ __forceinline__ void ldsm_x4(uint32_t addr, uint32_t& r0, uint32_t& r1,
                                        uint32_t& r2, uint32_t& r3) {
    asm volatile("ldmatrix.sync.aligned.m8n8.x4.shared.b16 {%0,%1,%2,%3}, [%4];"
                 : "=r"(r0), "=r"(r1), "=r"(r2), "=r"(r3) : "r"(addr));
}

__device__ __forceinline__ void lds128(uint32_t addr, uint32_t& x, uint32_t& y,
                                       uint32_t& z, uint32_t& w) {
    asm volatile("ld.shared.v4.b32 {%0,%1,%2,%3}, [%4];"
                 : "=r"(x), "=r"(y), "=r"(z), "=r"(w) : "r"(addr));
}
__device__ __forceinline__ void sts128(uint32_t a, uint32_t x, uint32_t y, uint32_t z, uint32_t w) {
    asm volatile("st.shared.v4.b32 [%0], {%1,%2,%3,%4};"
                 :: "r"(a), "r"(x), "r"(y), "r"(z), "r"(w) : "memory");
}

__device__ __forceinline__ void mma16816(float* c, const uint32_t* a, uint32_t b0, uint32_t b1) {
    asm volatile(
        "mma.sync.aligned.m16n8k16.row.col.f32.f16.f16.f32 "
        "{%0,%1,%2,%3}, {%4,%5,%6,%7}, {%8,%9}, {%0,%1,%2,%3};"
        : "+f"(c[0]), "+f"(c[1]), "+f"(c[2]), "+f"(c[3])
        : "r"(a[0]), "r"(a[1]), "r"(a[2]), "r"(a[3]), "r"(b0), "r"(b1));
}

__device__ __forceinline__ void split2(float v0, float v1, uint32_t& hi, uint32_t& lo) {
    __half h0 = __float2half_rn(v0), h1 = __float2half_rn(v1);
    __half2 hh = __halves2half2(h0, h1);
    hi = *(uint32_t*)&hh;
    __half2 ll = __floats2half2_rn(v0 - __half2float(h0), v1 - __half2float(h1));
    lo = *(uint32_t*)&ll;
}

// ============ device scratch ============

static constexpr size_t NEL = 16ull * 1024 * 1024;  // 16 x 1024 x 1024

__device__ __half g_w[NEL];     // softmax weights, fp16
__device__ __half g_et[NEL];    // E^T per batch, fp16: [b][d][k]
__device__ float  g_scores[NEL];

// fp16 MMA tile: 128 rows x 32 halves, padded stride 80 B -> conflict-free LDSM
static constexpr int ROWB = 80;
static constexpr int TILEB = 128 * ROWB;  // 10240 B

// ---- GEMM1 smem layout (k32, single staging + single tiles; R5-proven) ----
static constexpr int G1_ROW32 = 144;                 // fp32 staging row stride
static constexpr int G1_STG   = 128 * G1_ROW32;      // 18432 B per operand
static constexpr int G1_SA    = 0;
static constexpr int G1_SB    = G1_STG;
static constexpr int G1_TQH   = 2 * G1_STG;
static constexpr int G1_TQL   = G1_TQH + TILEB;
static constexpr int G1_TEH   = G1_TQH + 2 * TILEB;
static constexpr int G1_TEL   = G1_TQH + 3 * TILEB;
static constexpr int G1_SMEM  = G1_TQH + 4 * TILEB;  // 77824 B

// ============ GEMM1: scores = Q @ E^T, fp32 in, convert-in-kernel, 3-term split ============
// grid (9, 8, 16): bx 0..7 = compute CTAs (n-block), bx==8 = E^T helper CTAs.

__device__ __forceinline__ void g1_cp(uint32_t sb, int tid, int kc,
                                      const float* gQ, const float* gE) {
    #pragma unroll
    for (int i = 0; i < 4; i++) {
        int id = i * 256 + tid;           // 0..1023
        int row = id >> 3, seg = id & 7;
        uint32_t off = row * G1_ROW32 + seg * 16;
        size_t go = (size_t)row * 1024 + kc * 32 + seg * 4;
        cp_async16(sb + G1_SA + off, gQ + go);
        cp_async16(sb + G1_SB + off, gE + go);
    }
    CP_COMMIT();
}

__global__ void __launch_bounds__(256, 2)
gemm1_kernel(const float* __restrict__ Q, const float* __restrict__ E) {
    extern __shared__ char smem[];
    uint32_t sb = smem_u32(smem);
    int tid = threadIdx.x, wid = tid >> 5, lane = tid & 31;
    int b = blockIdx.z;
    size_t boff = (size_t)b << 20;

    // ---- E^T helper CTAs: convert-transpose E -> g_et for d-strip blockIdx.y ----
    if (blockIdx.x == 8) {
        __half* ts = (__half*)smem;                 // 64 x 65 halves scratch
        int f4id = tid & 15, rr = tid >> 4;
        int lane5 = tid >> 5;
        for (int t = 0; t < 32; t++) {
            int d0 = (blockIdx.y << 7) + (t & 1) * 64;
            int k0 = (t >> 1) << 6;
            #pragma unroll
            for (int pass = 0; pass < 4; pass++) {
                int k = pass * 16 + rr;
                float4 v = *(const float4*)(E + boff + (size_t)(k0 + k) * 1024 + d0 + f4id * 4);
                __half* rp = ts + k * 65 + f4id * 4;
                rp[0] = __float2half_rn(v.x);
                rp[1] = __float2half_rn(v.y);
                rp[2] = __float2half_rn(v.z);
                rp[3] = __float2half_rn(v.w);
            }
            __syncthreads();
            #pragma unroll
            for (int pass = 0; pass < 8; pass++) {
                int dd = pass * 8 + lane5;
                int kk = lane * 2;
                __half2 o = __halves2half2(ts[kk * 65 + dd], ts[(kk + 1) * 65 + dd]);
                *(__half2*)(g_et + boff + (size_t)(d0 + dd) * 1024 + k0 + kk) = o;
            }
            __syncthreads();
        }
        return;
    }

    int wm = wid >> 2, wn = wid & 3;
    int m0 = blockIdx.y << 7, n0 = blockIdx.x << 7;

    const float* gQ = Q + boff + (size_t)m0 * 1024;
    const float* gE = E + boff + (size_t)n0 * 1024;

    float c[4][4][4];
    #pragma unroll
    for (int i = 0; i < 4; i++)
        #pragma unroll
        for (int j = 0; j < 4; j++)
            #pragma unroll
            for (int k = 0; k < 4; k++) c[i][j][k] = 0.f;

    g1_cp(sb, tid, 0, gQ, gE);

    int lr = lane & 15;
    uint32_t lkoff = (lane >> 4) * 16;  // bytes

    // convert-thread mapping: each thread handles one half-row (16 elems) of A and B
    int cm = tid >> 1;
    int cko = (tid & 1) * 16;
    uint32_t csrc = cm * G1_ROW32 + cko * 4;
    uint32_t cdst = cm * 80 + cko * 2;

    for (int kc = 0; kc < 32; kc++) {
        CP_WAIT(0);
        __syncthreads();   // staging(kc) ready; MMA(kc-1) done -> tiles reusable

        // ---- convert staging -> fp16 hi/lo tiles ----
        {
            uint32_t ra[4][4], rb[4][4];
            #pragma unroll
            for (int j = 0; j < 4; j++)
                lds128(sb + G1_SA + csrc + j * 16, ra[j][0], ra[j][1], ra[j][2], ra[j][3]);
            #pragma unroll
            for (int j = 0; j < 4; j++)
                lds128(sb + G1_SB + csrc + j * 16, rb[j][0], rb[j][1], rb[j][2], rb[j][3]);

            uint32_t hi[8], lo[8];
            #pragma unroll
            for (int j = 0; j < 4; j++) {
                split2(__uint_as_float(ra[j][0]), __uint_as_float(ra[j][1]), hi[j * 2], lo[j * 2]);
                split2(__uint_as_float(ra[j][2]), __uint_as_float(ra[j][3]), hi[j * 2 + 1], lo[j * 2 + 1]);
            }
            sts128(sb + G1_TQH + cdst,      hi[0], hi[1], hi[2], hi[3]);
            sts128(sb + G1_TQH + cdst + 16, hi[4], hi[5], hi[6], hi[7]);
            sts128(sb + G1_TQL + cdst,      lo[0], lo[1], lo[2], lo[3]);
            sts128(sb + G1_TQL + cdst + 16, lo[4], lo[5], lo[6], lo[7]);
            #pragma unroll
            for (int j = 0; j < 4; j++) {
                split2(__uint_as_float(rb[j][0]), __uint_as_float(rb[j][1]), hi[j * 2], lo[j * 2]);
                split2(__uint_as_float(rb[j][2]), __uint_as_float(rb[j][3]), hi[j * 2 + 1], lo[j * 2 + 1]);
            }
            sts128(sb + G1_TEH + cdst,      hi[0], hi[1], hi[2], hi[3]);
            sts128(sb + G1_TEH + cdst + 16, hi[4], hi[5], hi[6], hi[7]);
            sts128(sb + G1_TEL + cdst,      lo[0], lo[1], lo[2], lo[3]);
            sts128(sb + G1_TEL + cdst + 16, lo[4], lo[5], lo[6], lo[7]);
        }
        __syncthreads();   // tiles ready; staging free for next cp

        if (kc + 1 < 32) g1_cp(sb, tid, kc + 1, gQ, gE);

        // ---- MMA phase ----
        #pragma unroll
        for (int ks = 0; ks < 2; ks++) {
            uint32_t koff = ks * 32 + lkoff;
            uint32_t bh[2][4], bl[2][4];
            #pragma unroll
            for (int p = 0; p < 2; p++) {
                uint32_t a = sb + G1_TEH + (wn * 32 + p * 16 + lr) * ROWB + koff;
                ldsm_x4(a, bh[p][0], bh[p][1], bh[p][2], bh[p][3]);
                ldsm_x4(a + TILEB, bl[p][0], bl[p][1], bl[p][2], bl[p][3]);
            }
            #pragma unroll
            for (int mt = 0; mt < 4; mt++) {
                uint32_t ah[4], al[4];
                uint32_t a = sb + G1_TQH + (wm * 64 + mt * 16 + lr) * ROWB + koff;
                ldsm_x4(a, ah[0], ah[1], ah[2], ah[3]);
                ldsm_x4(a + TILEB, al[0], al[1], al[2], al[3]);
                #pragma unroll
                for (int p = 0; p < 2; p++)
                    #pragma unroll
                    for (int q = 0; q < 2; q++) {
                        int nt = p * 2 + q;
                        mma16816(c[mt][nt], ah, bh[p][q], bh[p][q + 2]);
                        mma16816(c[mt][nt], ah, bl[p][q], bl[p][q + 2]);
                        mma16816(c[mt][nt], al, bh[p][q], bh[p][q + 2]);
                    }
            }
        }
    }

    int r0 = m0 + wm * 64 + (lane >> 2);
    int col = n0 + wn * 32 + (lane & 3) * 2;
    #pragma unroll
    for (int mt = 0; mt < 4; mt++)
        #pragma unroll
        for (int nt = 0; nt < 4; nt++) {
            size_t base = boff + (size_t)(r0 + mt * 16) * 1024 + col + nt * 8;
            *(float2*)(g_scores + base) = make_float2(c[mt][nt][0], c[mt][nt][1]);
            *(float2*)(g_scores + base + 8 * 1024) = make_float2(c[mt][nt][2], c[mt][nt][3]);
        }
}

// ============ softmax: fp32 rows of g_scores -> fp16 g_w ============

__global__ void __launch_bounds__(256)
softmax_kernel() {
    __shared__ float red[40];
    size_t row = blockIdx.x;
    const float4* p = (const float4*)(g_scores + (row << 10));
    int t = threadIdx.x, wid = t >> 5, lane = t & 31;

    float4 v = p[t];
    float m = fmaxf(fmaxf(v.x, v.y), fmaxf(v.z, v.w));
    #pragma unroll
    for (int o = 16; o; o >>= 1) m = fmaxf(m, __shfl_xor_sync(0xffffffffu, m, o));
    if (lane == 0) red[wid] = m;
    __syncthreads();
    if (t == 0) {
        float mm = red[0];
        #pragma unroll
        for (int i = 1; i < 8; i++) mm = fmaxf(mm, red[i]);
        red[8] = mm;
    }
    __syncthreads();
    float mx = red[8];

    float4 e = make_float4(__expf(v.x - mx), __expf(v.y - mx),
                           __expf(v.z - mx), __expf(v.w - mx));
    float s = e.x + e.y + e.z + e.w;
    #pragma unroll
    for (int o = 16; o; o >>= 1) s += __shfl_xor_sync(0xffffffffu, s, o);
    if (lane == 0) red[16 + wid] = s;
    __syncthreads();
    if (t == 0) {
        float ss = red[16];
        #pragma unroll
        for (int i = 1; i < 8; i++) ss += red[16 + i];
        red[24] = 1.0f / ss;
    }
    __syncthreads();
    float inv = red[24];

    __half2* w = (__half2*)(g_w + (row << 10));
    w[t * 2]     = __floats2half2_rn(e.x * inv, e.y * inv);
    w[t * 2 + 1] = __floats2half2_rn(e.z * inv, e.w * inv);
}

// ============ GEMM2: out = W @ V (pure fp16, 3-stage pipeline, g_et from gemm1) ============

__device__ __forceinline__ void g2_load(uint32_t base, int tid, int kc,
                                        const __half* gA, const __half* gB) {
    #pragma unroll
    for (int i = 0; i < 2; i++) {
        int cid = i * 256 + tid;
        int row = cid >> 2, seg = cid & 3;
        uint32_t off = row * ROWB + seg * 16;
        size_t go = (size_t)row * 1024 + kc * 32 + seg * 8;
        cp_async16(base + off, gA + go);
        cp_async16(base + TILEB + off, gB + go);
    }
    CP_COMMIT();
}

__global__ void __launch_bounds__(256, 2)
gemm2_kernel(float* __restrict__ O) {
    extern __shared__ char smem[];
    uint32_t sb = smem_u32(smem);
    int tid = threadIdx.x, wid = tid >> 5, lane = tid & 31;
    int wm = wid >> 2, wn = wid & 3;
    int b = blockIdx.z;
    int m0 = blockIdx.y << 7, n0 = blockIdx.x << 7;
    size_t boff = (size_t)b << 20;

    const __half* gA = g_w + boff + (size_t)m0 * 1024;
    const __half* gB = g_et + boff + (size_t)n0 * 1024;

    float c[4][4][4];
    #pragma unroll
    for (int i = 0; i < 4; i++)
        #pragma unroll
        for (int j = 0; j < 4; j++)
            #pragma unroll
            for (int k = 0; k < 4; k++) c[i][j][k] = 0.f;

    g2_load(sb + 0 * 2 * TILEB, tid, 0, gA, gB);
    g2_load(sb + 1 * 2 * TILEB, tid, 1, gA, gB);

    int lr = lane & 15;
    uint32_t lkoff = (lane >> 4) * 16;

    int slot = 0;
    for (int kc = 0; kc < 32; kc++) {
        if (kc < 31) { CP_WAIT(1); } else { CP_WAIT(0); }
        __syncthreads();

        uint32_t abase = sb + slot * 2 * TILEB;
        #pragma unroll
        for (int ks = 0; ks < 2; ks++) {
            uint32_t koff = ks * 32 + lkoff;
            uint32_t ah[4][4], bh[2][4];
            #pragma unroll
            for (int mt = 0; mt < 4; mt++) {
                uint32_t a = abase + (wm * 64 + mt * 16 + lr) * ROWB + koff;
                ldsm_x4(a, ah[mt][0], ah[mt][1], ah[mt][2], ah[mt][3]);
            }
            #pragma unroll
            for (int p = 0; p < 2; p++) {
                uint32_t a = abase + TILEB + (wn * 32 + p * 16 + lr) * ROWB + koff;
                ldsm_x4(a, bh[p][0], bh[p][1], bh[p][2], bh[p][3]);
            }
            #pragma unroll
            for (int mt = 0; mt < 4; mt++)
                #pragma unroll
                for (int p = 0; p < 2; p++)
                    #pragma unroll
                    for (int q = 0; q < 2; q++)
                        mma16816(c[mt][p * 2 + q], ah[mt], bh[p][q], bh[p][q + 2]);
        }

        if (kc + 2 < 32) {
            int ns = kc + 2 - ((kc + 2) / 3) * 3;  // (kc+2) % 3
            g2_load(sb + ns * 2 * TILEB, tid, kc + 2, gA, gB);
        }
        slot = (slot == 2) ? 0 : slot + 1;
    }

    int r0 = m0 + wm * 64 + (lane >> 2);
    int col = n0 + wn * 32 + (lane & 3) * 2;
    #pragma unroll
    for (int mt = 0; mt < 4; mt++)
        #pragma unroll
        for (int nt = 0; nt < 4; nt++) {
            size_t base = boff + (size_t)(r0 + mt * 16) * 1024 + col + nt * 8;
            *(float2*)(O + base) = make_float2(c[mt][nt][0], c[mt][nt][1]);
            *(float2*)(O + base + 8 * 1024) = make_float2(c[mt][nt][2], c[mt][nt][3]);
        }
}

// ============ launcher ============

extern "C" void kernel_launch(void* const* d_in, const int* in_sizes, int n_in,
                              void* d_out, int out_size) {
    const float* dec = (const float*)d_in[0];   // decoder_hidden  [16,1024,1024]
    const float* enc = (const float*)d_in[1];   // encoder_outputs [16,1024,1024]
    float* out = (float*)d_out;

    cudaFuncSetAttribute(gemm1_kernel, cudaFuncAttributeMaxDynamicSharedMemorySize, G1_SMEM);
    cudaFuncSetAttribute(gemm2_kernel, cudaFuncAttributeMaxDynamicSharedMemorySize, 6 * TILEB);

    gemm1_kernel<<<dim3(9, 8, 16), 256, G1_SMEM>>>(dec, enc);
    softmax_kernel<<<16384, 256>>>();
    gemm2_kernel<<<dim3(8, 8, 16), 256, 6 * TILEB>>>(out);
}

// round 10
// speedup vs baseline: 1.0802x; 1.0298x over previous
#include <cuda_runtime.h>
#include <cuda_fp16.h>
#include <cstdint>

// ============ helpers ============

__device__ __forceinline__ uint32_t smem_u32(const void* p) {
    uint32_t a;
    asm("{ .reg .u64 t; cvta.to.shared.u64 t, %1; cvt.u32.u64 %0, t; }" : "=r"(a) : "l"(p));
    return a;
}

__device__ __forceinline__ void cp_async16(uint32_t saddr, const void* gaddr) {
    asm volatile("cp.async.cg.shared.global [%0], [%1], 16;" :: "r"(saddr), "l"(gaddr));
}
#define CP_COMMIT() asm volatile("cp.async.commit_group;" ::: "memory")
#define CP_WAIT(N)  asm volatile("cp.async.wait_group %0;" :: "n"(N) : "memory")

__device__ __forceinline__ void ldsm_x4(uint32_t addr, uint32_t& r0, uint32_t& r1,
                                        uint32_t& r2, uint32_t& r3) {
    asm volatile("ldmatrix.sync.aligned.m8n8.x4.shared.b16 {%0,%1,%2,%3}, [%4];"
                 : "=r"(r0), "=r"(r1), "=r"(r2), "=r"(r3) : "r"(addr));
}

__device__ __forceinline__ void lds128(uint32_t addr, uint32_t& x, uint32_t& y,
                                       uint32_t& z, uint32_t& w) {
    asm volatile("ld.shared.v4.b32 {%0,%1,%2,%3}, [%4];"
                 : "=r"(x), "=r"(y), "=r"(z), "=r"(w) : "r"(addr));
}
__device__ __forceinline__ void sts128(uint32_t a, uint32_t x, uint32_t y, uint32_t z, uint32_t w) {
    asm volatile("st.shared.v4.b32 [%0], {%1,%2,%3,%4};"
                 :: "r"(a), "r"(x), "r"(y), "r"(z), "r"(w) : "memory");
}

__device__ __forceinline__ void mma16816(float* c, const uint32_t* a, uint32_t b0, uint32_t b1) {
    asm volatile(
        "mma.sync.aligned.m16n8k16.row.col.f32.f16.f16.f32 "
        "{%0,%1,%2,%3}, {%4,%5,%6,%7}, {%8,%9}, {%0,%1,%2,%3};"
        : "+f"(c[0]), "+f"(c[1]), "+f"(c[2]), "+f"(c[3])
        : "r"(a[0]), "r"(a[1]), "r"(a[2]), "r"(a[3]), "r"(b0), "r"(b1));
}

__device__ __forceinline__ void split2(float v0, float v1, uint32_t& hi, uint32_t& lo) {
    __half h0 = __float2half_rn(v0), h1 = __float2half_rn(v1);
    __half2 hh = __halves2half2(h0, h1);
    hi = *(uint32_t*)&hh;
    __half2 ll = __floats2half2_rn(v0 - __half2float(h0), v1 - __half2float(h1));
    lo = *(uint32_t*)&ll;
}

// ============ device scratch ============

static constexpr size_t NEL = 16ull * 1024 * 1024;  // 16 x 1024 x 1024

__device__ __half g_w[NEL];     // softmax weights, fp16
__device__ __half g_et[NEL];    // E^T per batch, fp16: [b][d][k]
__device__ float  g_scores[NEL];

// gemm1 fp16 MMA tile: 128 rows x 32 halves, stride 80 B (conflict-free)
static constexpr int ROWB = 80;
static constexpr int TILEB = 128 * ROWB;  // 10240 B

// ---- GEMM1 smem layout (k32, single staging + single tiles; R5-proven) ----
static constexpr int G1_ROW32 = 144;
static constexpr int G1_STG   = 128 * G1_ROW32;      // 18432 B per operand
static constexpr int G1_SA    = 0;
static constexpr int G1_SB    = G1_STG;
static constexpr int G1_TQH   = 2 * G1_STG;
static constexpr int G1_TQL   = G1_TQH + TILEB;
static constexpr int G1_TEH   = G1_TQH + 2 * TILEB;
static constexpr int G1_TEL   = G1_TQH + 3 * TILEB;
static constexpr int G1_SMEM  = G1_TQH + 4 * TILEB;  // 77824 B

// ---- GEMM2 smem layout (k64, 3-slot rotation) ----
static constexpr int G2_ROW  = 144;                  // 64 halves = 128B data + 16 pad
static constexpr int G2_TILE = 128 * G2_ROW;         // 18432 B per operand
static constexpr int G2_SMEM = 3 * 2 * G2_TILE;      // 110592 B (2 CTAs/SM: 216KB+res <= 228KB)

// ============ E transpose-convert: fp32 [b][k][d] -> fp16 g_et [b][d][k] ============

__global__ void __launch_bounds__(256)
et_kernel(const float* __restrict__ enc) {
    __shared__ __half ts[64][65];
    int b = blockIdx.z;
    int d0 = blockIdx.x << 6, k0 = blockIdx.y << 6;
    size_t boff = (size_t)b << 20;
    int tid = threadIdx.x;
    int f4id = tid & 15, rr = tid >> 4;

    #pragma unroll
    for (int pass = 0; pass < 4; pass++) {
        int k = pass * 16 + rr;
        size_t go = boff + (size_t)(k0 + k) * 1024 + d0 + f4id * 4;
        float4 v = *(const float4*)(enc + go);
        int dc = f4id * 4;
        ts[k][dc]     = __float2half_rn(v.x);
        ts[k][dc + 1] = __float2half_rn(v.y);
        ts[k][dc + 2] = __float2half_rn(v.z);
        ts[k][dc + 3] = __float2half_rn(v.w);
    }
    __syncthreads();
    int lane = tid & 31;
    #pragma unroll
    for (int pass = 0; pass < 8; pass++) {
        int dd = pass * 8 + (tid >> 5);
        int kk = lane * 2;
        __half2 o = __halves2half2(ts[kk][dd], ts[kk + 1][dd]);
        *(__half2*)(g_et + boff + (size_t)(d0 + dd) * 1024 + k0 + kk) = o;
    }
}

// ============ GEMM1: scores = Q @ E^T, fp32 in, convert-in-kernel, 3-term split ============

__device__ __forceinline__ void g1_cp(uint32_t sb, int tid, int kc,
                                      const float* gQ, const float* gE) {
    #pragma unroll
    for (int i = 0; i < 4; i++) {
        int id = i * 256 + tid;           // 0..1023
        int row = id >> 3, seg = id & 7;
        uint32_t off = row * G1_ROW32 + seg * 16;
        size_t go = (size_t)row * 1024 + kc * 32 + seg * 4;
        cp_async16(sb + G1_SA + off, gQ + go);
        cp_async16(sb + G1_SB + off, gE + go);
    }
    CP_COMMIT();
}

__global__ void __launch_bounds__(256, 2)
gemm1_kernel(const float* __restrict__ Q, const float* __restrict__ E) {
    extern __shared__ char smem[];
    uint32_t sb = smem_u32(smem);
    int tid = threadIdx.x, wid = tid >> 5, lane = tid & 31;
    int wm = wid >> 2, wn = wid & 3;
    int b = blockIdx.z;
    int m0 = blockIdx.y << 7, n0 = blockIdx.x << 7;
    size_t boff = (size_t)b << 20;

    const float* gQ = Q + boff + (size_t)m0 * 1024;
    const float* gE = E + boff + (size_t)n0 * 1024;

    float c[4][4][4];
    #pragma unroll
    for (int i = 0; i < 4; i++)
        #pragma unroll
        for (int j = 0; j < 4; j++)
            #pragma unroll
            for (int k = 0; k < 4; k++) c[i][j][k] = 0.f;

    g1_cp(sb, tid, 0, gQ, gE);

    int lr = lane & 15;
    uint32_t lkoff = (lane >> 4) * 16;  // bytes

    int cm = tid >> 1;
    int cko = (tid & 1) * 16;
    uint32_t csrc = cm * G1_ROW32 + cko * 4;
    uint32_t cdst = cm * 80 + cko * 2;

    for (int kc = 0; kc < 32; kc++) {
        CP_WAIT(0);
        __syncthreads();   // staging(kc) ready; MMA(kc-1) done -> tiles reusable

        // ---- convert staging -> fp16 hi/lo tiles ----
        {
            uint32_t ra[4][4], rb[4][4];
            #pragma unroll
            for (int j = 0; j < 4; j++)
                lds128(sb + G1_SA + csrc + j * 16, ra[j][0], ra[j][1], ra[j][2], ra[j][3]);
            #pragma unroll
            for (int j = 0; j < 4; j++)
                lds128(sb + G1_SB + csrc + j * 16, rb[j][0], rb[j][1], rb[j][2], rb[j][3]);

            uint32_t hi[8], lo[8];
            #pragma unroll
            for (int j = 0; j < 4; j++) {
                split2(__uint_as_float(ra[j][0]), __uint_as_float(ra[j][1]), hi[j * 2], lo[j * 2]);
                split2(__uint_as_float(ra[j][2]), __uint_as_float(ra[j][3]), hi[j * 2 + 1], lo[j * 2 + 1]);
            }
            sts128(sb + G1_TQH + cdst,      hi[0], hi[1], hi[2], hi[3]);
            sts128(sb + G1_TQH + cdst + 16, hi[4], hi[5], hi[6], hi[7]);
            sts128(sb + G1_TQL + cdst,      lo[0], lo[1], lo[2], lo[3]);
            sts128(sb + G1_TQL + cdst + 16, lo[4], lo[5], lo[6], lo[7]);
            #pragma unroll
            for (int j = 0; j < 4; j++) {
                split2(__uint_as_float(rb[j][0]), __uint_as_float(rb[j][1]), hi[j * 2], lo[j * 2]);
                split2(__uint_as_float(rb[j][2]), __uint_as_float(rb[j][3]), hi[j * 2 + 1], lo[j * 2 + 1]);
            }
            sts128(sb + G1_TEH + cdst,      hi[0], hi[1], hi[2], hi[3]);
            sts128(sb + G1_TEH + cdst + 16, hi[4], hi[5], hi[6], hi[7]);
            sts128(sb + G1_TEL + cdst,      lo[0], lo[1], lo[2], lo[3]);
            sts128(sb + G1_TEL + cdst + 16, lo[4], lo[5], lo[6], lo[7]);
        }
        __syncthreads();   // tiles ready; staging free for next cp

        if (kc + 1 < 32) g1_cp(sb, tid, kc + 1, gQ, gE);

        // ---- MMA phase ----
        #pragma unroll
        for (int ks = 0; ks < 2; ks++) {
            uint32_t koff = ks * 32 + lkoff;
            uint32_t bh[2][4], bl[2][4];
            #pragma unroll
            for (int p = 0; p < 2; p++) {
                uint32_t a = sb + G1_TEH + (wn * 32 + p * 16 + lr) * ROWB + koff;
                ldsm_x4(a, bh[p][0], bh[p][1], bh[p][2], bh[p][3]);
                ldsm_x4(a + TILEB, bl[p][0], bl[p][1], bl[p][2], bl[p][3]);
            }
            #pragma unroll
            for (int mt = 0; mt < 4; mt++) {
                uint32_t ah[4], al[4];
                uint32_t a = sb + G1_TQH + (wm * 64 + mt * 16 + lr) * ROWB + koff;
                ldsm_x4(a, ah[0], ah[1], ah[2], ah[3]);
                ldsm_x4(a + TILEB, al[0], al[1], al[2], al[3]);
                #pragma unroll
                for (int p = 0; p < 2; p++)
                    #pragma unroll
                    for (int q = 0; q < 2; q++) {
                        int nt = p * 2 + q;
                        mma16816(c[mt][nt], ah, bh[p][q], bh[p][q + 2]);
                        mma16816(c[mt][nt], ah, bl[p][q], bl[p][q + 2]);
                        mma16816(c[mt][nt], al, bh[p][q], bh[p][q + 2]);
                    }
            }
        }
    }

    int r0 = m0 + wm * 64 + (lane >> 2);
    int col = n0 + wn * 32 + (lane & 3) * 2;
    #pragma unroll
    for (int mt = 0; mt < 4; mt++)
        #pragma unroll
        for (int nt = 0; nt < 4; nt++) {
            size_t base = boff + (size_t)(r0 + mt * 16) * 1024 + col + nt * 8;
            *(float2*)(g_scores + base) = make_float2(c[mt][nt][0], c[mt][nt][1]);
            *(float2*)(g_scores + base + 8 * 1024) = make_float2(c[mt][nt][2], c[mt][nt][3]);
        }
}

// ============ softmax: fp32 rows of g_scores -> fp16 g_w ============

__global__ void __launch_bounds__(256)
softmax_kernel() {
    __shared__ float red[40];
    size_t row = blockIdx.x;
    const float4* p = (const float4*)(g_scores + (row << 10));
    int t = threadIdx.x, wid = t >> 5, lane = t & 31;

    float4 v = p[t];
    float m = fmaxf(fmaxf(v.x, v.y), fmaxf(v.z, v.w));
    #pragma unroll
    for (int o = 16; o; o >>= 1) m = fmaxf(m, __shfl_xor_sync(0xffffffffu, m, o));
    if (lane == 0) red[wid] = m;
    __syncthreads();
    if (t == 0) {
        float mm = red[0];
        #pragma unroll
        for (int i = 1; i < 8; i++) mm = fmaxf(mm, red[i]);
        red[8] = mm;
    }
    __syncthreads();
    float mx = red[8];

    float4 e = make_float4(__expf(v.x - mx), __expf(v.y - mx),
                           __expf(v.z - mx), __expf(v.w - mx));
    float s = e.x + e.y + e.z + e.w;
    #pragma unroll
    for (int o = 16; o; o >>= 1) s += __shfl_xor_sync(0xffffffffu, s, o);
    if (lane == 0) red[16 + wid] = s;
    __syncthreads();
    if (t == 0) {
        float ss = red[16];
        #pragma unroll
        for (int i = 1; i < 8; i++) ss += red[16 + i];
        red[24] = 1.0f / ss;
    }
    __syncthreads();
    float inv = red[24];

    __half2* w = (__half2*)(g_w + (row << 10));
    w[t * 2]     = __floats2half2_rn(e.x * inv, e.y * inv);
    w[t * 2 + 1] = __floats2half2_rn(e.z * inv, e.w * inv);
}

// ============ GEMM2: out = W @ V (pure fp16, k-chunk 64, 3-slot rotation) ============

__device__ __forceinline__ void g2_load(uint32_t base, int tid, int kc,
                                        const __half* gA, const __half* gB) {
    #pragma unroll
    for (int i = 0; i < 4; i++) {
        int id = i * 256 + tid;            // 0..1023
        int row = id >> 3, seg = id & 7;
        uint32_t off = row * G2_ROW + seg * 16;
        size_t go = (size_t)row * 1024 + kc * 64 + seg * 8;
        cp_async16(base + off, gA + go);
        cp_async16(base + G2_TILE + off, gB + go);
    }
    CP_COMMIT();
}

__global__ void __launch_bounds__(256, 2)
gemm2_kernel(float* __restrict__ O) {
    extern __shared__ char smem[];
    uint32_t sb = smem_u32(smem);
    int tid = threadIdx.x, wid = tid >> 5, lane = tid & 31;
    int wm = wid >> 2, wn = wid & 3;
    int b = blockIdx.z;
    int m0 = blockIdx.y << 7, n0 = blockIdx.x << 7;
    size_t boff = (size_t)b << 20;

    const __half* gA = g_w + boff + (size_t)m0 * 1024;
    const __half* gB = g_et + boff + (size_t)n0 * 1024;

    float c[4][4][4];
    #pragma unroll
    for (int i = 0; i < 4; i++)
        #pragma unroll
        for (int j = 0; j < 4; j++)
            #pragma unroll
            for (int k = 0; k < 4; k++) c[i][j][k] = 0.f;

    g2_load(sb + 0 * 2 * G2_TILE, tid, 0, gA, gB);
    g2_load(sb + 1 * 2 * G2_TILE, tid, 1, gA, gB);

    int lr = lane & 15;
    uint32_t lkoff = (lane >> 4) * 16;

    int slot = 0;
    for (int kc = 0; kc < 16; kc++) {
        if (kc < 15) { CP_WAIT(1); } else { CP_WAIT(0); }
        __syncthreads();

        uint32_t abase = sb + slot * 2 * G2_TILE;
        #pragma unroll
        for (int ks = 0; ks < 4; ks++) {
            uint32_t koff = ks * 32 + lkoff;
            uint32_t ah[4][4], bh[2][4];
            #pragma unroll
            for (int mt = 0; mt < 4; mt++) {
                uint32_t a = abase + (wm * 64 + mt * 16 + lr) * G2_ROW + koff;
                ldsm_x4(a, ah[mt][0], ah[mt][1], ah[mt][2], ah[mt][3]);
            }
            #pragma unroll
            for (int p = 0; p < 2; p++) {
                uint32_t a = abase + G2_TILE + (wn * 32 + p * 16 + lr) * G2_ROW + koff;
                ldsm_x4(a, bh[p][0], bh[p][1], bh[p][2], bh[p][3]);
            }
            #pragma unroll
            for (int mt = 0; mt < 4; mt++)
                #pragma unroll
                for (int p = 0; p < 2; p++)
                    #pragma unroll
                    for (int q = 0; q < 2; q++)
                        mma16816(c[mt][p * 2 + q], ah[mt], bh[p][q], bh[p][q + 2]);
        }

        if (kc + 2 < 16) {
            int ns = kc + 2 - ((kc + 2) / 3) * 3;  // (kc+2) % 3
            g2_load(sb + ns * 2 * G2_TILE, tid, kc + 2, gA, gB);
        }
        slot = (slot == 2) ? 0 : slot + 1;
    }

    int r0 = m0 + wm * 64 + (lane >> 2);
    int col = n0 + wn * 32 + (lane & 3) * 2;
    #pragma unroll
    for (int mt = 0; mt < 4; mt++)
        #pragma unroll
        for (int nt = 0; nt < 4; nt++) {
            size_t base = boff + (size_t)(r0 + mt * 16) * 1024 + col + nt * 8;
            *(float2*)(O + base) = make_float2(c[mt][nt][0], c[mt][nt][1]);
            *(float2*)(O + base + 8 * 1024) = make_float2(c[mt][nt][2], c[mt][nt][3]);
        }
}

// ============ launcher ============

extern "C" void kernel_launch(void* const* d_in, const int* in_sizes, int n_in,
                              void* d_out, int out_size) {
    const float* dec = (const float*)d_in[0];   // decoder_hidden  [16,1024,1024]
    const float* enc = (const float*)d_in[1];   // encoder_outputs [16,1024,1024]
    float* out = (float*)d_out;

    cudaFuncSetAttribute(gemm1_kernel, cudaFuncAttributeMaxDynamicSharedMemorySize, G1_SMEM);
    cudaFuncSetAttribute(gemm2_kernel, cudaFuncAttributeMaxDynamicSharedMemorySize, G2_SMEM);

    et_kernel<<<dim3(16, 16, 16), 256>>>(enc);
    gemm1_kernel<<<dim3(8, 8, 16), 256, G1_SMEM>>>(dec, enc);
    softmax_kernel<<<16384, 256>>>();
    gemm2_kernel<<<dim3(8, 8, 16), 256, G2_SMEM>>>(out);
}